// round 1
// baseline (speedup 1.0000x reference)
#include <cuda_runtime.h>
#include <math.h>
#include <stdint.h>

// Problem constants
#define BATCHN 32
#define SEQ    512
#define HIDDEN 1024
#define NHEADS 12
#define HDIM   64
#define NTOT   (NHEADS * HDIM * 2)   // 1536
#define MTOT   (BATCHN * SEQ)        // 16384
#define BIGINF 100000000.0f

// Scratch for rotated q/k in [b][h][s][d] layout (50.3 MB each, static — no allocs)
__device__ float g_q[(size_t)BATCHN * NHEADS * SEQ * HDIM];
__device__ float g_k[(size_t)BATCHN * NHEADS * SEQ * HDIM];

// ---------- packed fp32x2 helpers (Blackwell FFMA2: 2x fp32 throughput) ----------
__device__ __forceinline__ unsigned long long pack2(float lo, float hi) {
    unsigned long long r;
    asm("mov.b64 %0, {%1,%2};" : "=l"(r) : "f"(lo), "f"(hi));
    return r;
}
__device__ __forceinline__ void unpack2(unsigned long long v, float &lo, float &hi) {
    asm("mov.b64 {%0,%1}, %2;" : "=f"(lo), "=f"(hi) : "l"(v));
}
__device__ __forceinline__ void fma2(unsigned long long &d, unsigned long long a, unsigned long long b) {
    asm("fma.rn.f32x2 %0, %1, %2, %0;" : "+l"(d) : "l"(a), "l"(b));
}

// =====================================================================
// Kernel 1: x = hidden @ W^T + b, fused RoPE, scatter to g_q / g_k
// Tiles: BM=128, BN=128 (== one head: 64 q cols + 64 k cols), BK=16.
// 256 threads, 8x8 outputs/thread via f32x2 pairs (pairs along M).
// RoPE partner x[d^32] obtained by __shfl_xor(.., 4) (col tile flips bit 5).
// =====================================================================
__global__ __launch_bounds__(256, 2)
void qkv_rope_kernel(const float* __restrict__ hid,
                     const float* __restrict__ W,
                     const float* __restrict__ bias) {
    __shared__ __align__(16) float As[2][16][132];
    __shared__ __align__(16) float Bs[2][16][132];

    const int tid  = threadIdx.x;
    const int tx   = tid & 15;      // N direction (16 * 8 = 128)
    const int ty   = tid >> 4;      // M direction (16 * 8 = 128)
    const int m0   = blockIdx.y * 128;
    const int head = blockIdx.x;    // BN==128 so block n-range == one head
    const int n0   = head * 128;

    // gmem loader mapping: each thread loads 2 float4 for A and 2 for B
    const int lr   = tid >> 2;        // 0..63 (row)
    const int lc4  = (tid & 3) * 4;   // 0,4,8,12 (col within 16-wide k tile)

    float4 ra0, ra1, rb0, rb1;

    const float* Abase = hid + (size_t)(m0 + lr) * HIDDEN + lc4;
    const float* Bbase = W   + (size_t)(n0 + lr) * HIDDEN + lc4;

    // prologue load (kt = 0)
    ra0 = *(const float4*)(Abase);
    ra1 = *(const float4*)(Abase + (size_t)64 * HIDDEN);
    rb0 = *(const float4*)(Bbase);
    rb1 = *(const float4*)(Bbase + (size_t)64 * HIDDEN);

    {
        As[0][lc4+0][lr] = ra0.x; As[0][lc4+1][lr] = ra0.y; As[0][lc4+2][lr] = ra0.z; As[0][lc4+3][lr] = ra0.w;
        As[0][lc4+0][lr+64] = ra1.x; As[0][lc4+1][lr+64] = ra1.y; As[0][lc4+2][lr+64] = ra1.z; As[0][lc4+3][lr+64] = ra1.w;
        Bs[0][lc4+0][lr] = rb0.x; Bs[0][lc4+1][lr] = rb0.y; Bs[0][lc4+2][lr] = rb0.z; Bs[0][lc4+3][lr] = rb0.w;
        Bs[0][lc4+0][lr+64] = rb1.x; Bs[0][lc4+1][lr+64] = rb1.y; Bs[0][lc4+2][lr+64] = rb1.z; Bs[0][lc4+3][lr+64] = rb1.w;
    }
    __syncthreads();

    unsigned long long acc[4][8] = {};   // pairs along M: acc[i][j] = rows (2i, 2i+1), col j

    for (int kt = 0; kt < 64; kt++) {
        const int cur = kt & 1;
        if (kt < 63) {
            const float* Ap = Abase + (size_t)(kt + 1) * 16;
            const float* Bp = Bbase + (size_t)(kt + 1) * 16;
            ra0 = *(const float4*)(Ap);
            ra1 = *(const float4*)(Ap + (size_t)64 * HIDDEN);
            rb0 = *(const float4*)(Bp);
            rb1 = *(const float4*)(Bp + (size_t)64 * HIDDEN);
        }

        #pragma unroll
        for (int k = 0; k < 16; k++) {
            float4 a0 = *(const float4*)&As[cur][k][ty * 8];
            float4 a1 = *(const float4*)&As[cur][k][ty * 8 + 4];
            float4 b0 = *(const float4*)&Bs[cur][k][tx * 8];
            float4 b1 = *(const float4*)&Bs[cur][k][tx * 8 + 4];
            union U { float4 f; unsigned long long u[2]; };
            U ua0; ua0.f = a0;
            U ua1; ua1.f = a1;
            unsigned long long aa[4] = { ua0.u[0], ua0.u[1], ua1.u[0], ua1.u[1] };
            unsigned long long bb[8] = {
                pack2(b0.x, b0.x), pack2(b0.y, b0.y), pack2(b0.z, b0.z), pack2(b0.w, b0.w),
                pack2(b1.x, b1.x), pack2(b1.y, b1.y), pack2(b1.z, b1.z), pack2(b1.w, b1.w)
            };
            #pragma unroll
            for (int i = 0; i < 4; i++)
                #pragma unroll
                for (int j = 0; j < 8; j++)
                    fma2(acc[i][j], aa[i], bb[j]);
        }

        if (kt < 63) {
            const int nxt = cur ^ 1;
            As[nxt][lc4+0][lr] = ra0.x; As[nxt][lc4+1][lr] = ra0.y; As[nxt][lc4+2][lr] = ra0.z; As[nxt][lc4+3][lr] = ra0.w;
            As[nxt][lc4+0][lr+64] = ra1.x; As[nxt][lc4+1][lr+64] = ra1.y; As[nxt][lc4+2][lr+64] = ra1.z; As[nxt][lc4+3][lr+64] = ra1.w;
            Bs[nxt][lc4+0][lr] = rb0.x; Bs[nxt][lc4+1][lr] = rb0.y; Bs[nxt][lc4+2][lr] = rb0.z; Bs[nxt][lc4+3][lr] = rb0.w;
            Bs[nxt][lc4+0][lr+64] = rb1.x; Bs[nxt][lc4+1][lr+64] = rb1.y; Bs[nxt][lc4+2][lr+64] = rb1.z; Bs[nxt][lc4+3][lr+64] = rb1.w;
        }
        __syncthreads();
    }

    // ---------------- epilogue: bias + RoPE + scatter ----------------
    float val[8][8];
    #pragma unroll
    for (int i = 0; i < 4; i++)
        #pragma unroll
        for (int j = 0; j < 8; j++)
            unpack2(acc[i][j], val[2*i][j], val[2*i+1][j]);

    #pragma unroll
    for (int j = 0; j < 8; j++) {
        float bj = bias[n0 + tx * 8 + j];
        #pragma unroll
        for (int r = 0; r < 8; r++) val[r][j] += bj;
    }

    // inv_freq(d & 31) = 10000^(-(d&31)/32); d = (tx*8+j) & 63
    float invf[8];
    #pragma unroll
    for (int j = 0; j < 8; j++) {
        int fidx = (tx * 8 + j) & 31;
        invf[j] = exp2f((float)fidx * (-13.28771237954945f / 32.0f));
    }

    const int  b_idx = m0 / SEQ;            // tile never crosses batch boundary (128 | 512)
    const bool is_k  = (tx >= 8);           // cols 0..63 = q, 64..127 = k of this head
    float* dstbase = (is_k ? g_k : g_q)
                   + ((size_t)(b_idx * NHEADS + head) * SEQ) * HDIM + (tx & 7) * 8;

    #pragma unroll
    for (int r = 0; r < 8; r++) {
        const int s = (m0 + ty * 8 + r) & (SEQ - 1);
        float o[8];
        #pragma unroll
        for (int j = 0; j < 8; j++) {
            float x = val[r][j];
            // lane^4 flips tx bit 2 -> column bit 5 -> d^32 (partner for rotate_half)
            float p = __shfl_xor_sync(0xffffffffu, x, 4);
            int d = (tx * 8 + j) & 63;
            float sv, cv;
            sincosf((float)s * invf[j], &sv, &cv);
            float sign = (d < 32) ? -1.0f : 1.0f;
            o[j] = x * cv + sign * p * sv;
        }
        float* dst = dstbase + (size_t)s * HDIM;
        *(float4*)(dst)     = make_float4(o[0], o[1], o[2], o[3]);
        *(float4*)(dst + 4) = make_float4(o[4], o[5], o[6], o[7]);
    }
}

// =====================================================================
// Kernel 2: scores[b,h,m,n] = (q.k)/8, attention mask, strict-lower-tri = -1e8
// 64x64 tiles over 512x512, K=64 single-shot. Lower tiles: fast -1e8 fill.
// =====================================================================
__global__ __launch_bounds__(256)
void scores_kernel(const int* __restrict__ am, float* __restrict__ out) {
    const int nt = blockIdx.x, mt = blockIdx.y, bh = blockIdx.z;
    const int tid = threadIdx.x;
    float* obase = out + ((size_t)bh * SEQ + mt * 64) * SEQ + nt * 64;

    if (nt < mt) {   // entire tile strictly below diagonal -> exactly -1e8
        const float4 f = make_float4(-BIGINF, -BIGINF, -BIGINF, -BIGINF);
        #pragma unroll
        for (int i = 0; i < 4; i++) {
            int e = tid + i * 256;
            int r = e >> 4, c4 = (e & 15) * 4;
            *(float4*)(obase + (size_t)r * SEQ + c4) = f;
        }
        return;
    }

    __shared__ __align__(16) float qsT[64][68];
    __shared__ __align__(16) float ksT[64][68];

    const float* qsl = g_q + (size_t)bh * SEQ * HDIM + (size_t)mt * 64 * HDIM;
    const float* ksl = g_k + (size_t)bh * SEQ * HDIM + (size_t)nt * 64 * HDIM;

    #pragma unroll
    for (int i = 0; i < 4; i++) {
        int e = tid + i * 256;
        int r = e >> 4, c4 = (e & 15) * 4;
        float4 v = *(const float4*)(qsl + (size_t)r * HDIM + c4);
        qsT[c4+0][r] = v.x; qsT[c4+1][r] = v.y; qsT[c4+2][r] = v.z; qsT[c4+3][r] = v.w;
        float4 w = *(const float4*)(ksl + (size_t)r * HDIM + c4);
        ksT[c4+0][r] = w.x; ksT[c4+1][r] = w.y; ksT[c4+2][r] = w.z; ksT[c4+3][r] = w.w;
    }
    __syncthreads();

    const int tx = tid & 15, ty = tid >> 4;   // 4 cols, 4 rows per thread
    unsigned long long acc[2][4] = {};

    #pragma unroll 8
    for (int k = 0; k < 64; k++) {
        float4 a = *(const float4*)&qsT[k][ty * 4];
        float4 b = *(const float4*)&ksT[k][tx * 4];
        union U { float4 f; unsigned long long u[2]; };
        U ua; ua.f = a;
        unsigned long long bb[4] = { pack2(b.x,b.x), pack2(b.y,b.y), pack2(b.z,b.z), pack2(b.w,b.w) };
        #pragma unroll
        for (int i = 0; i < 2; i++)
            #pragma unroll
            for (int j = 0; j < 4; j++)
                fma2(acc[i][j], ua.u[i], bb[j]);
    }

    float val[4][4];
    #pragma unroll
    for (int i = 0; i < 2; i++)
        #pragma unroll
        for (int j = 0; j < 4; j++)
            unpack2(acc[i][j], val[2*i][j], val[2*i+1][j]);

    const int b_idx = bh / NHEADS;
    const int mrow0 = mt * 64 + ty * 4;
    const int ncol0 = nt * 64 + tx * 4;

    float mn[4];
    #pragma unroll
    for (int j = 0; j < 4; j++) mn[j] = (float)am[b_idx * SEQ + ncol0 + j];

    #pragma unroll
    for (int r = 0; r < 4; r++) {
        const int m = mrow0 + r;
        const float mm = (float)am[b_idx * SEQ + m];
        float o[4];
        #pragma unroll
        for (int j = 0; j < 4; j++) {
            float v = val[r][j] * 0.125f;                  // 1/sqrt(64)
            float msk = mm * mn[j];
            v = v * msk - BIGINF * (1.0f - msk);
            if (ncol0 + j < m) v = -BIGINF;                // tril(k=-1) mask
            o[j] = v;
        }
        *(float4*)(obase + (size_t)(ty * 4 + r) * SEQ + tx * 4)
            = make_float4(o[0], o[1], o[2], o[3]);
    }
}

// =====================================================================
extern "C" void kernel_launch(void* const* d_in, const int* in_sizes, int n_in,
                              void* d_out, int out_size) {
    const float* hid  = (const float*)d_in[0];   // (32, 512, 1024) fp32
    const int*   am   = (const int*)  d_in[1];   // (32, 512) int32
    const float* W    = (const float*)d_in[2];   // (1536, 1024) fp32
    const float* bias = (const float*)d_in[3];   // (1536,) fp32
    float* out = (float*)d_out;                  // (32, 12, 512, 512) fp32

    dim3 g1(NTOT / 128, MTOT / 128);             // (12, 128)
    qkv_rope_kernel<<<g1, 256>>>(hid, W, bias);

    dim3 g2(SEQ / 64, SEQ / 64, BATCHN * NHEADS); // (8, 8, 384)
    scores_kernel<<<g2, 256>>>(am, out);
}

// round 3
// speedup vs baseline: 4.2596x; 4.2596x over previous
#include <cuda_runtime.h>
#include <cuda_bf16.h>
#include <math.h>
#include <stdint.h>

#define BATCHN 32
#define SEQ    512
#define HIDDEN 1024
#define NHEADS 12
#define HDIM   64
#define BIGINF 100000000.0f

// ---------------- static device scratch (no allocs) ----------------
__device__ __nv_bfloat16 g_hbf[(size_t)16384 * 1024];               // hidden bf16 (32MB)
__device__ __nv_bfloat16 g_wbf[(size_t)1536 * 1024];                // W bf16 (3MB)
__device__ __nv_bfloat16 g_q[(size_t)BATCHN * NHEADS * SEQ * HDIM]; // rope'd q bf16 (24MB)
__device__ __nv_bfloat16 g_k[(size_t)BATCHN * NHEADS * SEQ * HDIM]; // rope'd k bf16 (24MB)

// ---------------- warp MMA helpers (sm_80+ path, valid on sm_100) ----------------
__device__ __forceinline__ uint32_t smem_u32(const void* p) {
    uint32_t a;
    asm("{ .reg .u64 t; cvta.to.shared.u64 t, %1; cvt.u32.u64 %0, t; }" : "=r"(a) : "l"(p));
    return a;
}
__device__ __forceinline__ void ldmx4(uint32_t* r, uint32_t addr) {
    asm volatile("ldmatrix.sync.aligned.m8n8.x4.shared.b16 {%0,%1,%2,%3}, [%4];"
                 : "=r"(r[0]), "=r"(r[1]), "=r"(r[2]), "=r"(r[3]) : "r"(addr));
}
__device__ __forceinline__ void mma16816(float* d, const uint32_t* a, const uint32_t* b) {
    asm volatile(
        "mma.sync.aligned.m16n8k16.row.col.f32.bf16.bf16.f32 "
        "{%0,%1,%2,%3}, {%4,%5,%6,%7}, {%8,%9}, {%0,%1,%2,%3};"
        : "+f"(d[0]), "+f"(d[1]), "+f"(d[2]), "+f"(d[3])
        : "r"(a[0]), "r"(a[1]), "r"(a[2]), "r"(a[3]), "r"(b[0]), "r"(b[1]));
}

// ---------------- kernel 0: fp32 -> bf16 ----------------
__global__ void cvt_kernel(const float4* __restrict__ src, uint2* __restrict__ dst, int n4) {
    for (int i = blockIdx.x * blockDim.x + threadIdx.x; i < n4; i += gridDim.x * blockDim.x) {
        float4 f = src[i];
        __nv_bfloat162 lo = __floats2bfloat162_rn(f.x, f.y);
        __nv_bfloat162 hi = __floats2bfloat162_rn(f.z, f.w);
        uint2 u;
        u.x = *reinterpret_cast<uint32_t*>(&lo);
        u.y = *reinterpret_cast<uint32_t*>(&hi);
        dst[i] = u;
    }
}

// =====================================================================
// Kernel 1: QKV GEMM (HMMA bf16) + bias + RoPE -> g_q / g_k
// CTA 128x128 (N tile == one head: 64 q + 64 k cols), BK=32 double-buffered.
// 8 warps, warp tile 32x64 (warp grid 4M x 2N). RoPE pairing (d, d+32) is
// n-fragment pair (f, f+4) within the same thread -> register-only epilogue.
// =====================================================================
__global__ __launch_bounds__(256, 2)
void qkv_mma_kernel(const float* __restrict__ bias) {
    __shared__ __align__(16) __nv_bfloat16 As[2][128][40];
    __shared__ __align__(16) __nv_bfloat16 Bs[2][128][40];

    const int tid  = threadIdx.x;
    const int lane = tid & 31;
    const int warp = tid >> 5;
    const int wm   = (warp >> 1) * 32;      // warp M offset in tile
    const int wn   = (warp & 1) * 64;       // warp N offset (0 = q half, 64 = k half)

    const int head = blockIdx.x;
    const int m0   = blockIdx.y * 128;
    const int n0   = head * 128;

    // loader: each thread moves 2 uint4 per matrix per k-tile
    const int lrow = tid >> 2;              // 0..63
    const int lc   = (tid & 3) * 8;         // bf16 col {0,8,16,24}
    const __nv_bfloat16* Aptr = g_hbf + (size_t)(m0 + lrow) * HIDDEN + lc;
    const __nv_bfloat16* Bptr = g_wbf + (size_t)(n0 + lrow) * HIDDEN + lc;

    uint4 ra0, ra1, rb0, rb1;
    // prologue load kt=0
    ra0 = *(const uint4*)(Aptr);
    ra1 = *(const uint4*)(Aptr + (size_t)64 * HIDDEN);
    rb0 = *(const uint4*)(Bptr);
    rb1 = *(const uint4*)(Bptr + (size_t)64 * HIDDEN);
    *(uint4*)&As[0][lrow][lc]      = ra0;
    *(uint4*)&As[0][lrow + 64][lc] = ra1;
    *(uint4*)&Bs[0][lrow][lc]      = rb0;
    *(uint4*)&Bs[0][lrow + 64][lc] = rb1;
    __syncthreads();

    float acc[2][8][4];
    #pragma unroll
    for (int i = 0; i < 2; i++)
        #pragma unroll
        for (int j = 0; j < 8; j++)
            #pragma unroll
            for (int e = 0; e < 4; e++) acc[i][j][e] = 0.0f;

    const int l15 = lane & 15, lhi = lane >> 4;   // A ldmatrix addressing
    const int g   = lane >> 3, l7 = lane & 7;     // B ldmatrix addressing

    for (int kt = 0; kt < 32; kt++) {
        const int buf = kt & 1;
        if (kt < 31) {
            const __nv_bfloat16* Ap = Aptr + (kt + 1) * 32;
            const __nv_bfloat16* Bp = Bptr + (kt + 1) * 32;
            ra0 = *(const uint4*)(Ap);
            ra1 = *(const uint4*)(Ap + (size_t)64 * HIDDEN);
            rb0 = *(const uint4*)(Bp);
            rb1 = *(const uint4*)(Bp + (size_t)64 * HIDDEN);
        }

        #pragma unroll
        for (int ks = 0; ks < 2; ks++) {
            const int k0 = ks * 16;
            uint32_t af[2][4];
            #pragma unroll
            for (int mf = 0; mf < 2; mf++)
                ldmx4(af[mf], smem_u32(&As[buf][wm + mf * 16 + l15][k0 + 8 * lhi]));
            uint32_t bfr[8][2];
            #pragma unroll
            for (int p = 0; p < 4; p++) {
                uint32_t r[4];
                ldmx4(r, smem_u32(&Bs[buf][wn + p * 16 + (g >> 1) * 8 + l7][k0 + (g & 1) * 8]));
                bfr[2 * p][0] = r[0]; bfr[2 * p][1] = r[1];
                bfr[2 * p + 1][0] = r[2]; bfr[2 * p + 1][1] = r[3];
            }
            #pragma unroll
            for (int mf = 0; mf < 2; mf++)
                #pragma unroll
                for (int nf = 0; nf < 8; nf++)
                    mma16816(acc[mf][nf], af[mf], bfr[nf]);
        }

        if (kt < 31) {
            const int nxt = buf ^ 1;
            *(uint4*)&As[nxt][lrow][lc]      = ra0;
            *(uint4*)&As[nxt][lrow + 64][lc] = ra1;
            *(uint4*)&Bs[nxt][lrow][lc]      = rb0;
            *(uint4*)&Bs[nxt][lrow + 64][lc] = rb1;
            __syncthreads();
        }
    }

    // ---------------- epilogue: bias + RoPE, register-only ----------------
    const int qg = lane >> 2, tc = lane & 3;
    const int b  = m0 >> 9;                               // batch (128 | 512)
    __nv_bfloat16* dstbase = ((wn == 0) ? g_q : g_k)
                           + (size_t)(b * NHEADS + head) * SEQ * HDIM;
    const float C = -0.41524101186092029f;                // -log2(10000)/32

    #pragma unroll
    for (int mf = 0; mf < 2; mf++) {
        #pragma unroll
        for (int rh = 0; rh < 2; rh++) {
            const int s = (m0 + wm + mf * 16 + qg + rh * 8) & (SEQ - 1);
            __nv_bfloat16* drow = dstbase + (size_t)s * HDIM;
            #pragma unroll
            for (int f = 0; f < 4; f++) {
                float o0[2], o1[2];
                #pragma unroll
                for (int e = 0; e < 2; e++) {
                    const int d = f * 8 + tc * 2 + e;     // 0..31
                    float x0 = acc[mf][f][rh * 2 + e]     + __ldg(&bias[n0 + wn + d]);
                    float x1 = acc[mf][f + 4][rh * 2 + e] + __ldg(&bias[n0 + wn + d + 32]);
                    float sv, cv;
                    sincosf((float)s * exp2f((float)d * C), &sv, &cv);
                    o0[e] = x0 * cv - x1 * sv;            // out[d]
                    o1[e] = x1 * cv + x0 * sv;            // out[d+32]
                }
                __nv_bfloat162 p0 = __floats2bfloat162_rn(o0[0], o0[1]);
                __nv_bfloat162 p1 = __floats2bfloat162_rn(o1[0], o1[1]);
                *(uint32_t*)&drow[f * 8 + tc * 2]      = *(uint32_t*)&p0;
                *(uint32_t*)&drow[f * 8 + tc * 2 + 32] = *(uint32_t*)&p1;
            }
        }
    }
}

// =====================================================================
// Kernel 2: scores = (q.kT)/8 + masks. CTA 128x128, K=64 single-shot HMMA.
// Strict-lower tiles short-circuit to vectorized -1e8 fills.
// =====================================================================
__global__ __launch_bounds__(256, 2)
void scores_mma_kernel(const int* __restrict__ am, float* __restrict__ out) {
    const int nt = blockIdx.x, mt = blockIdx.y, bh = blockIdx.z;
    const int tid = threadIdx.x, lane = tid & 31, warp = tid >> 5;
    float* ob = out + ((size_t)bh * SEQ + mt * 128) * SEQ + nt * 128;

    if (nt < mt) {   // whole tile strictly below diagonal -> exact -1e8
        const float4 f = make_float4(-BIGINF, -BIGINF, -BIGINF, -BIGINF);
        #pragma unroll
        for (int t = 0; t < 16; t++) {
            int e = tid + t * 256;
            int row = e >> 5, c4 = (e & 31) * 4;
            *(float4*)(ob + (size_t)row * SEQ + c4) = f;
        }
        return;
    }

    __shared__ __align__(16) __nv_bfloat16 Qs[128][72];
    __shared__ __align__(16) __nv_bfloat16 Ks[128][72];

    const __nv_bfloat16* Qsrc = g_q + ((size_t)bh * SEQ + mt * 128) * HDIM;
    const __nv_bfloat16* Ksrc = g_k + ((size_t)bh * SEQ + nt * 128) * HDIM;

    #pragma unroll
    for (int t = 0; t < 4; t++) {
        int idx = tid + t * 256;                 // 0..1023
        int row = idx >> 3, c = (idx & 7) * 8;
        *(uint4*)&Qs[row][c] = *(const uint4*)(Qsrc + (size_t)row * HDIM + c);
        *(uint4*)&Ks[row][c] = *(const uint4*)(Ksrc + (size_t)row * HDIM + c);
    }
    __syncthreads();

    const int wm = (warp >> 1) * 32, wn = (warp & 1) * 64;
    const int l15 = lane & 15, lhi = lane >> 4;
    const int g = lane >> 3, l7 = lane & 7;

    float acc[2][8][4];
    #pragma unroll
    for (int i = 0; i < 2; i++)
        #pragma unroll
        for (int j = 0; j < 8; j++)
            #pragma unroll
            for (int e = 0; e < 4; e++) acc[i][j][e] = 0.0f;

    #pragma unroll
    for (int ks = 0; ks < 4; ks++) {
        const int k0 = ks * 16;
        uint32_t af[2][4];
        #pragma unroll
        for (int mf = 0; mf < 2; mf++)
            ldmx4(af[mf], smem_u32(&Qs[wm + mf * 16 + l15][k0 + 8 * lhi]));
        uint32_t bfr[8][2];
        #pragma unroll
        for (int p = 0; p < 4; p++) {
            uint32_t r[4];
            ldmx4(r, smem_u32(&Ks[wn + p * 16 + (g >> 1) * 8 + l7][k0 + (g & 1) * 8]));
            bfr[2 * p][0] = r[0]; bfr[2 * p][1] = r[1];
            bfr[2 * p + 1][0] = r[2]; bfr[2 * p + 1][1] = r[3];
        }
        #pragma unroll
        for (int mf = 0; mf < 2; mf++)
            #pragma unroll
            for (int nf = 0; nf < 8; nf++)
                mma16816(acc[mf][nf], af[mf], bfr[nf]);
    }

    // epilogue: scale, attention mask, tril(k=-1) mask
    const int qg = lane >> 2, tc = lane & 3;
    const int b  = bh / NHEADS;

    #pragma unroll
    for (int mf = 0; mf < 2; mf++) {
        #pragma unroll
        for (int rh = 0; rh < 2; rh++) {
            const int m = mt * 128 + wm + mf * 16 + qg + rh * 8;
            const float mm = (float)__ldg(&am[b * SEQ + m]);
            float* orow = out + ((size_t)bh * SEQ + m) * SEQ;
            #pragma unroll
            for (int f = 0; f < 8; f++) {
                const int nc = nt * 128 + wn + f * 8 + tc * 2;
                float2 v;
                float* vp = &v.x;
                #pragma unroll
                for (int e = 0; e < 2; e++) {
                    const int n = nc + e;
                    float x = acc[mf][f][rh * 2 + e] * 0.125f;   // 1/sqrt(64)
                    float msk = mm * (float)__ldg(&am[b * SEQ + n]);
                    x = x * msk - BIGINF * (1.0f - msk);
                    if (n < m) x = -BIGINF;                      // tril(k=-1)
                    vp[e] = x;
                }
                *(float2*)&orow[nc] = v;
            }
        }
    }
}

// ---------------- launch ----------------
extern "C" void kernel_launch(void* const* d_in, const int* in_sizes, int n_in,
                              void* d_out, int out_size) {
    const float* hid  = (const float*)d_in[0];   // (32, 512, 1024) fp32
    const int*   am   = (const int*)  d_in[1];   // (32, 512) int32
    const float* W    = (const float*)d_in[2];   // (1536, 1024) fp32
    const float* bias = (const float*)d_in[3];   // (1536,) fp32
    float* out = (float*)d_out;                  // (32, 12, 512, 512) fp32

    __nv_bfloat16 *hbf_p, *wbf_p;
    cudaGetSymbolAddress((void**)&hbf_p, g_hbf);
    cudaGetSymbolAddress((void**)&wbf_p, g_wbf);

    cvt_kernel<<<1024, 256>>>((const float4*)hid, (uint2*)hbf_p, 16384 * 1024 / 4);
    cvt_kernel<<<384, 256>>>((const float4*)W,    (uint2*)wbf_p, 1536 * 1024 / 4);

    dim3 g1(NHEADS, 16384 / 128);                     // (12, 128)
    qkv_mma_kernel<<<g1, 256>>>(bias);

    dim3 g2(SEQ / 128, SEQ / 128, BATCHN * NHEADS);   // (4, 4, 384)
    scores_mma_kernel<<<g2, 256>>>(am, out);
}